// round 2
// baseline (speedup 1.0000x reference)
#include <cuda_runtime.h>
#include <math.h>

// Problem constants
#define BB   4
#define SQL  512
#define SKL  512
#define DD   512
#define HH   8
#define DHH  64
#define BHH  32          // B*H
#define MR   2048        // B*SQ

// Scratch (device globals; no allocation allowed)
__device__ float g_qh[MR * DD];
__device__ float g_kh[MR * DD];
__device__ float g_vh[MR * DD];
__device__ float g_T [SQL * BHH * DD];   // [q][bh][e]
__device__ float g_c [MR * HH];          // [(b*SQ+q)*H + h]
__device__ float g_att[MR * DD];
__device__ float g_o2 [MR * DD];

// Canonical uint8 masks + dtype mode flag
__device__ unsigned char g_am [SQL * SKL];
__device__ unsigned char g_kpm[BB * SKL];
__device__ int g_mask_mode;   // 0=int32, 1=uint8, 2=float32

// ---------------------------------------------------------------------------
// Mask dtype detection: inspect attn_mask byte pattern.
//   uint8 bool  -> nonzero bytes appear at positions %4==1 (causal runs of 1s)
//   float32 1.0 -> bytes {00,00,80,3F}: nonzero only at %4 in {2,3}
//   int32 1     -> nonzero only at %4==0
// Single block; writes g_mask_mode. Only reads the first SQL*SKL BYTES, which
// is in-bounds for every candidate dtype.
// ---------------------------------------------------------------------------
__global__ void mask_detect(const unsigned char* __restrict__ am)
{
    unsigned int or1 = 0, or23 = 0;
    const uint4* p = (const uint4*)am;
    int n16 = SQL * SKL / 16;
    for (int i = threadIdx.x; i < n16; i += blockDim.x) {
        uint4 v = p[i];
        or1  |= (v.x & 0x0000FF00u) | (v.y & 0x0000FF00u) | (v.z & 0x0000FF00u) | (v.w & 0x0000FF00u);
        or23 |= (v.x & 0xFFFF0000u) | (v.y & 0xFFFF0000u) | (v.z & 0xFFFF0000u) | (v.w & 0xFFFF0000u);
    }
    int any1  = __syncthreads_or((int)(or1 != 0));
    int any23 = __syncthreads_or((int)(or23 != 0));
    if (threadIdx.x == 0) {
        g_mask_mode = any1 ? 1 : (any23 ? 2 : 0);
    }
}

__global__ void mask_convert(const unsigned char* __restrict__ am,
                             const unsigned char* __restrict__ kpm)
{
    int mode = g_mask_mode;
    int stride = gridDim.x * blockDim.x;
    int tid = blockIdx.x * blockDim.x + threadIdx.x;
    for (int i = tid; i < SQL * SKL; i += stride) {
        unsigned char v;
        if (mode == 1)      v = (am[i] != 0);
        else if (mode == 2) v = (((const float*)am)[i] != 0.0f);
        else                v = (((const int*)am)[i] != 0);
        g_am[i] = v;
    }
    for (int i = tid; i < BB * SKL; i += stride) {
        unsigned char v;
        if (mode == 1)      v = (kpm[i] != 0);
        else if (mode == 2) v = (((const float*)kpm)[i] != 0.0f);
        else                v = (((const int*)kpm)[i] != 0);
        g_kpm[i] = v;
    }
}

// ---------------------------------------------------------------------------
// Generic tiled SGEMM: C[M,N] = A[M,K] @ W[K,N] + bias[N] (+ optional residual)
// BM=BN=64, BK=16, 256 threads, 4x4 register tile per thread.
// ---------------------------------------------------------------------------
__global__ void sgemm_bias(const float* __restrict__ A, const float* __restrict__ W,
                           const float* __restrict__ bias, const float* __restrict__ resid,
                           float* __restrict__ C, int M, int N, int K)
{
    __shared__ float As[16][64];   // [k][m]  (A stored transposed)
    __shared__ float Ws[16][64];   // [k][n]
    int tid = threadIdx.x;
    int tx = tid & 15, ty = tid >> 4;
    int row0 = blockIdx.y * 64;
    int col0 = blockIdx.x * 64;
    float acc[4][4] = {};

    int la_r = tid >> 2;          // 0..63 (m)
    int la_c = (tid & 3) * 4;     // 0..12 (k)
    int lw_r = tid >> 4;          // 0..15 (k)
    int lw_c = (tid & 15) * 4;    // 0..60 (n)

    for (int k0 = 0; k0 < K; k0 += 16) {
        float4 a4 = *(const float4*)(A + (size_t)(row0 + la_r) * K + k0 + la_c);
        As[la_c + 0][la_r] = a4.x;
        As[la_c + 1][la_r] = a4.y;
        As[la_c + 2][la_r] = a4.z;
        As[la_c + 3][la_r] = a4.w;
        float4 w4 = *(const float4*)(W + (size_t)(k0 + lw_r) * N + col0 + lw_c);
        *(float4*)&Ws[lw_r][lw_c] = w4;
        __syncthreads();
        #pragma unroll
        for (int kk = 0; kk < 16; kk++) {
            float a[4], b[4];
            #pragma unroll
            for (int i = 0; i < 4; i++) a[i] = As[kk][ty * 4 + i];
            #pragma unroll
            for (int j = 0; j < 4; j++) b[j] = Ws[kk][tx * 4 + j];
            #pragma unroll
            for (int i = 0; i < 4; i++)
                #pragma unroll
                for (int j = 0; j < 4; j++)
                    acc[i][j] += a[i] * b[j];
        }
        __syncthreads();
    }
    #pragma unroll
    for (int i = 0; i < 4; i++) {
        int r = row0 + ty * 4 + i;
        #pragma unroll
        for (int j = 0; j < 4; j++) {
            int c = col0 + tx * 4 + j;
            float vv = acc[i][j] + bias[c];
            if (resid) vv += resid[(size_t)r * N + c];
            C[(size_t)r * N + c] = vv;
        }
    }
}

// ---------------------------------------------------------------------------
// t[b,q,h,e] = sum_d (qh[b,q,h,d]+v_bias[h,d]) * Wr[e, h*64+d]
// Stored as g_T[((q*32) + b*8 + h)*512 + e].
// ---------------------------------------------------------------------------
__global__ void t_kernel(const float* __restrict__ Wr, const float* __restrict__ vb)
{
    __shared__ float As[16][64];   // [d][m]
    __shared__ float Ws[16][64];   // [d][e]
    int h = blockIdx.z, hoff = h * DHH;
    int m0 = blockIdx.y * 64, e0 = blockIdx.x * 64;
    int tid = threadIdx.x;
    int tx = tid & 15, ty = tid >> 4;
    int lr = tid >> 2, lc = (tid & 3) * 4;
    float acc[4][4] = {};

    for (int d0 = 0; d0 < DHH; d0 += 16) {
        float4 a4 = *(const float4*)(g_qh + (size_t)(m0 + lr) * DD + hoff + d0 + lc);
        float4 v4 = *(const float4*)(vb + hoff + d0 + lc);
        As[lc + 0][lr] = a4.x + v4.x;
        As[lc + 1][lr] = a4.y + v4.y;
        As[lc + 2][lr] = a4.z + v4.z;
        As[lc + 3][lr] = a4.w + v4.w;
        float4 w4 = *(const float4*)(Wr + (size_t)(e0 + lr) * DD + hoff + d0 + lc);
        Ws[lc + 0][lr] = w4.x;
        Ws[lc + 1][lr] = w4.y;
        Ws[lc + 2][lr] = w4.z;
        Ws[lc + 3][lr] = w4.w;
        __syncthreads();
        #pragma unroll
        for (int kk = 0; kk < 16; kk++) {
            float a[4], b[4];
            #pragma unroll
            for (int i = 0; i < 4; i++) a[i] = As[kk][ty * 4 + i];
            #pragma unroll
            for (int j = 0; j < 4; j++) b[j] = Ws[kk][tx * 4 + j];
            #pragma unroll
            for (int i = 0; i < 4; i++)
                #pragma unroll
                for (int j = 0; j < 4; j++)
                    acc[i][j] += a[i] * b[j];
        }
        __syncthreads();
    }
    #pragma unroll
    for (int i = 0; i < 4; i++) {
        int mm = m0 + ty * 4 + i;
        int b = mm >> 9, qq = mm & 511;
        float4 sv = {acc[i][0], acc[i][1], acc[i][2], acc[i][3]};
        *(float4*)(g_T + ((size_t)qq * BHH + b * HH + h) * DD + e0 + tx * 4) = sv;
    }
}

// c[b,q,h] = sum_d (qh+v_bias) * br_h
__global__ void c_kernel(const float* __restrict__ vb, const float* __restrict__ br)
{
    int idx = blockIdx.x * blockDim.x + threadIdx.x;
    if (idx >= MR * HH) return;
    int h = idx & 7;
    int m = idx >> 3;
    int hoff = h * DHH;
    const float* qrow = g_qh + (size_t)m * DD + hoff;
    float s = 0.f;
    #pragma unroll 8
    for (int d = 0; d < DHH; d++)
        s += (qrow[d] + vb[hoff + d]) * br[hoff + d];
    g_c[idx] = s;
}

// ---------------------------------------------------------------------------
// ac[b,h,q,k] -> raw into score buffer. Skips fully masked 64x64 tiles.
// ---------------------------------------------------------------------------
__global__ void ac_kernel(const float* __restrict__ ub,
                          float* __restrict__ score)
{
    __shared__ float As[16][64];
    __shared__ float Ks[16][64];
    int bh = blockIdx.z, b = bh >> 3, h = bh & 7, hoff = h * DHH;
    int q0 = blockIdx.y * 64, k0 = blockIdx.x * 64;
    int tid = threadIdx.x;
    int tx = tid & 15, ty = tid >> 4;

    const unsigned char* rp = g_am + (size_t)(q0 + (tid >> 2)) * SKL + k0 + (tid & 3) * 16;
    int allm = 1;
    #pragma unroll
    for (int j = 0; j < 16; j++) allm &= (rp[j] != 0);
    if (__syncthreads_and(allm)) return;

    int lr = tid >> 2, lc = (tid & 3) * 4;
    float acc[4][4] = {};
    for (int d0 = 0; d0 < DHH; d0 += 16) {
        float4 a4 = *(const float4*)(g_qh + ((size_t)b * SQL + q0 + lr) * DD + hoff + d0 + lc);
        float4 u4 = *(const float4*)(ub + hoff + d0 + lc);
        As[lc + 0][lr] = a4.x + u4.x;
        As[lc + 1][lr] = a4.y + u4.y;
        As[lc + 2][lr] = a4.z + u4.z;
        As[lc + 3][lr] = a4.w + u4.w;
        float4 k4 = *(const float4*)(g_kh + ((size_t)b * SQL + k0 + lr) * DD + hoff + d0 + lc);
        Ks[lc + 0][lr] = k4.x;
        Ks[lc + 1][lr] = k4.y;
        Ks[lc + 2][lr] = k4.z;
        Ks[lc + 3][lr] = k4.w;
        __syncthreads();
        #pragma unroll
        for (int kk = 0; kk < 16; kk++) {
            float a[4], bv[4];
            #pragma unroll
            for (int i = 0; i < 4; i++) a[i] = As[kk][ty * 4 + i];
            #pragma unroll
            for (int j = 0; j < 4; j++) bv[j] = Ks[kk][tx * 4 + j];
            #pragma unroll
            for (int i = 0; i < 4; i++)
                #pragma unroll
                for (int j = 0; j < 4; j++)
                    acc[i][j] += a[i] * bv[j];
        }
        __syncthreads();
    }
    #pragma unroll
    for (int i = 0; i < 4; i++) {
        float4 sv = {acc[i][0], acc[i][1], acc[i][2], acc[i][3]};
        *(float4*)(score + ((size_t)bh * SQL + q0 + ty * 4 + i) * SKL + k0 + tx * 4) = sv;
    }
}

// ---------------------------------------------------------------------------
// bd kernel: score[bh,q,k] = (ac + sum_e T[q][bh][e]*pos_emb[q,k,e] + c)/8
// ---------------------------------------------------------------------------
__global__ void bd_kernel(const float* __restrict__ pos_emb,
                          float* __restrict__ score)
{
    const int EC = 32;
    __shared__ float Ts[32][EC + 1];
    __shared__ float Ps[64][EC + 1];
    int q = blockIdx.y;
    int k0 = blockIdx.x * 64;
    int tid = threadIdx.x;

    int allm = g_am[(size_t)q * SKL + k0 + (tid & 63)] != 0;
    if (__syncthreads_and(allm)) return;

    int kg = tid & 15;
    int bg = tid >> 4;
    float acc0[4] = {0.f, 0.f, 0.f, 0.f};
    float acc1[4] = {0.f, 0.f, 0.f, 0.f};

    const float* Tbase = g_T + (size_t)q * BHH * DD;
    const float* Pbase = pos_emb + ((size_t)q * SKL + k0) * DD;
    int lr = tid >> 3;
    int le = (tid & 7) * 4;

    for (int e0 = 0; e0 < DD; e0 += EC) {
        float4 t4 = *(const float4*)(Tbase + (size_t)lr * DD + e0 + le);
        Ts[lr][le + 0] = t4.x; Ts[lr][le + 1] = t4.y;
        Ts[lr][le + 2] = t4.z; Ts[lr][le + 3] = t4.w;
        float4 p4 = *(const float4*)(Pbase + (size_t)lr * DD + e0 + le);
        Ps[lr][le + 0] = p4.x; Ps[lr][le + 1] = p4.y;
        Ps[lr][le + 2] = p4.z; Ps[lr][le + 3] = p4.w;
        float4 p5 = *(const float4*)(Pbase + (size_t)(lr + 32) * DD + e0 + le);
        Ps[lr + 32][le + 0] = p5.x; Ps[lr + 32][le + 1] = p5.y;
        Ps[lr + 32][le + 2] = p5.z; Ps[lr + 32][le + 3] = p5.w;
        __syncthreads();
        #pragma unroll
        for (int e = 0; e < EC; e++) {
            float a0 = Ts[bg * 2 + 0][e];
            float a1 = Ts[bg * 2 + 1][e];
            #pragma unroll
            for (int j = 0; j < 4; j++) {
                float bv = Ps[kg * 4 + j][e];
                acc0[j] += a0 * bv;
                acc1[j] += a1 * bv;
            }
        }
        __syncthreads();
    }

    #pragma unroll
    for (int i = 0; i < 2; i++) {
        int bh = bg * 2 + i;
        int b = bh >> 3, h = bh & 7;
        float cc = g_c[((size_t)b * SQL + q) * HH + h];
        float* acc = i ? acc1 : acc0;
        float* srow = score + ((size_t)bh * SQL + q) * SKL + k0 + kg * 4;
        float4 sv = *(float4*)srow;
        sv.x = (sv.x + acc[0] + cc) * 0.125f;
        sv.y = (sv.y + acc[1] + cc) * 0.125f;
        sv.z = (sv.z + acc[2] + cc) * 0.125f;
        sv.w = (sv.w + acc[3] + cc) * 0.125f;
        *(float4*)srow = sv;
    }
}

// ---------------------------------------------------------------------------
// Masked softmax per (b,h,q) row; writes attn_weights in place.
// ---------------------------------------------------------------------------
__global__ void softmax_kernel(float* __restrict__ score)
{
    int row = blockIdx.x;          // bh*SQ + q
    int q = row & 511;
    int bh = row >> 9;
    int b = bh >> 3;
    int tid = threadIdx.x;         // 128
    float* s = score + (size_t)row * SKL;

    float4 v4 = *(float4*)(s + tid * 4);
    float vals[4] = {v4.x, v4.y, v4.z, v4.w};
    const unsigned char* amr = g_am + (size_t)q * SKL + tid * 4;
    const unsigned char* kpr = g_kpm + (size_t)b * SKL + tid * 4;
    #pragma unroll
    for (int j = 0; j < 4; j++)
        if (amr[j] || kpr[j]) vals[j] = -INFINITY;

    float mx = fmaxf(fmaxf(vals[0], vals[1]), fmaxf(vals[2], vals[3]));
    #pragma unroll
    for (int off = 16; off; off >>= 1)
        mx = fmaxf(mx, __shfl_xor_sync(0xffffffffu, mx, off));
    __shared__ float sm[4], ssum[4];
    int wid = tid >> 5, lane = tid & 31;
    if (lane == 0) sm[wid] = mx;
    __syncthreads();
    mx = fmaxf(fmaxf(sm[0], sm[1]), fmaxf(sm[2], sm[3]));

    float e[4]; float sum = 0.f;
    #pragma unroll
    for (int j = 0; j < 4; j++) {
        e[j] = (vals[j] == -INFINITY) ? 0.f : __expf(vals[j] - mx);
        sum += e[j];
    }
    #pragma unroll
    for (int off = 16; off; off >>= 1)
        sum += __shfl_xor_sync(0xffffffffu, sum, off);
    if (lane == 0) ssum[wid] = sum;
    __syncthreads();
    sum = ssum[0] + ssum[1] + ssum[2] + ssum[3];
    float inv = (sum > 0.f) ? 1.f / sum : 0.f;
    float4 o = {e[0] * inv, e[1] * inv, e[2] * inv, e[3] * inv};
    *(float4*)(s + tid * 4) = o;
}

// ---------------------------------------------------------------------------
// AV: att[b,q,h,d] = sum_k w[bh,q,k] * vh[b,k,h,d]. Skips all-masked k chunks.
// ---------------------------------------------------------------------------
__global__ void av_kernel(const float* __restrict__ score)
{
    __shared__ float As[16][64];   // [k][q]
    __shared__ float Ws[16][64];   // [k][d]
    int bh = blockIdx.y, b = bh >> 3, h = bh & 7, hoff = h * DHH;
    int q0 = blockIdx.x * 64;
    int tid = threadIdx.x;
    int tx = tid & 15, ty = tid >> 4;
    float acc[4][4] = {};

    int la_q = tid >> 2, la_k = (tid & 3) * 4;
    int lw_k = tid >> 4, lw_d = (tid & 15) * 4;

    for (int k0 = 0; k0 < SKL; k0 += 16) {
        const unsigned char* rp = g_am + (size_t)(q0 + (tid >> 2)) * SKL + k0 + (tid & 3) * 4;
        int allm = (rp[0] && rp[1] && rp[2] && rp[3]);
        if (__syncthreads_and(allm)) continue;

        float4 a4 = *(const float4*)(score + ((size_t)bh * SQL + q0 + la_q) * SKL + k0 + la_k);
        As[la_k + 0][la_q] = a4.x;
        As[la_k + 1][la_q] = a4.y;
        As[la_k + 2][la_q] = a4.z;
        As[la_k + 3][la_q] = a4.w;
        float4 w4 = *(const float4*)(g_vh + ((size_t)b * SQL + k0 + lw_k) * DD + hoff + lw_d);
        *(float4*)&Ws[lw_k][lw_d] = w4;
        __syncthreads();
        #pragma unroll
        for (int kk = 0; kk < 16; kk++) {
            float a[4], bv[4];
            #pragma unroll
            for (int i = 0; i < 4; i++) a[i] = As[kk][ty * 4 + i];
            #pragma unroll
            for (int j = 0; j < 4; j++) bv[j] = Ws[kk][tx * 4 + j];
            #pragma unroll
            for (int i = 0; i < 4; i++)
                #pragma unroll
                for (int j = 0; j < 4; j++)
                    acc[i][j] += a[i] * bv[j];
        }
        __syncthreads();
    }
    #pragma unroll
    for (int i = 0; i < 4; i++) {
        float4 sv = {acc[i][0], acc[i][1], acc[i][2], acc[i][3]};
        *(float4*)(g_att + ((size_t)b * SQL + q0 + ty * 4 + i) * DD + hoff + tx * 4) = sv;
    }
}

// ---------------------------------------------------------------------------
// LayerNorm per row of 512 (population variance, eps=1e-5)
// ---------------------------------------------------------------------------
__global__ void ln_kernel(const float* __restrict__ X, const float* __restrict__ gamma,
                          const float* __restrict__ beta, float* __restrict__ out)
{
    int row = blockIdx.x;
    int tid = threadIdx.x;  // 256
    const float* x = X + (size_t)row * DD;
    float2 v = *(const float2*)(x + tid * 2);
    float s = v.x + v.y;
    float s2 = v.x * v.x + v.y * v.y;
    #pragma unroll
    for (int off = 16; off; off >>= 1) {
        s  += __shfl_xor_sync(0xffffffffu, s, off);
        s2 += __shfl_xor_sync(0xffffffffu, s2, off);
    }
    __shared__ float rs[8], rs2[8];
    int wid = tid >> 5, lane = tid & 31;
    if (lane == 0) { rs[wid] = s; rs2[wid] = s2; }
    __syncthreads();
    s = 0.f; s2 = 0.f;
    #pragma unroll
    for (int i = 0; i < 8; i++) { s += rs[i]; s2 += rs2[i]; }
    float mean = s * (1.f / DD);
    float var = s2 * (1.f / DD) - mean * mean;
    float inv = rsqrtf(var + 1e-5f);
    float2 g2 = *(const float2*)(gamma + tid * 2);
    float2 b2 = *(const float2*)(beta + tid * 2);
    float2 o;
    o.x = (v.x - mean) * inv * g2.x + b2.x;
    o.y = (v.y - mean) * inv * g2.y + b2.y;
    *(float2*)(out + (size_t)row * DD + tid * 2) = o;
}

// ---------------------------------------------------------------------------
extern "C" void kernel_launch(void* const* d_in, const int* in_sizes, int n_in,
                              void* d_out, int out_size)
{
    const float* q  = (const float*)d_in[0];
    const float* k  = (const float*)d_in[1];
    const float* v  = (const float*)d_in[2];
    const float* pe = (const float*)d_in[3];
    const unsigned char* kpm = (const unsigned char*)d_in[4];
    const unsigned char* am  = (const unsigned char*)d_in[5];
    const float* Wq = (const float*)d_in[6];
    const float* bq = (const float*)d_in[7];
    const float* Wk = (const float*)d_in[8];
    const float* bk = (const float*)d_in[9];
    const float* Wv = (const float*)d_in[10];
    const float* bv = (const float*)d_in[11];
    const float* Wo = (const float*)d_in[12];
    const float* bo = (const float*)d_in[13];
    const float* Wr = (const float*)d_in[14];
    const float* br = (const float*)d_in[15];
    const float* ub = (const float*)d_in[16];
    const float* vb = (const float*)d_in[17];
    const float* lg = (const float*)d_in[18];
    const float* lb = (const float*)d_in[19];

    float* normed = (float*)d_out;
    float* attnw  = normed + (size_t)BB * SQL * DD;

    float *att;
    cudaGetSymbolAddress((void**)&att, g_att);
    float *o2;
    cudaGetSymbolAddress((void**)&o2, g_o2);
    float *qh, *kh, *vh;
    cudaGetSymbolAddress((void**)&qh, g_qh);
    cudaGetSymbolAddress((void**)&kh, g_kh);
    cudaGetSymbolAddress((void**)&vh, g_vh);

    // Normalize masks (dtype-agnostic)
    mask_detect<<<1, 1024>>>(am);
    mask_convert<<<64, 256>>>(am, kpm);

    sgemm_bias<<<dim3(8, 32), 256>>>(q, Wq, bq, nullptr, qh, MR, DD, DD);
    sgemm_bias<<<dim3(8, 32), 256>>>(k, Wk, bk, nullptr, kh, MR, DD, DD);
    sgemm_bias<<<dim3(8, 32), 256>>>(v, Wv, bv, nullptr, vh, MR, DD, DD);

    c_kernel<<<(MR * HH + 255) / 256, 256>>>(vb, br);
    t_kernel<<<dim3(8, 32, 8), 256>>>(Wr, vb);

    ac_kernel<<<dim3(8, 8, 32), 256>>>(ub, attnw);
    bd_kernel<<<dim3(8, 512), 256>>>(pe, attnw);
    softmax_kernel<<<BHH * SQL, 128>>>(attnw);

    av_kernel<<<dim3(8, 32), 256>>>(attnw);

    sgemm_bias<<<dim3(8, 32), 256>>>(att, Wo, bo, q, o2, MR, DD, DD);
    ln_kernel<<<MR, 256>>>(o2, lg, lb, normed);
}